// round 16
// baseline (speedup 1.0000x reference)
#include <cuda_runtime.h>
#include <math.h>

#define Hf 128
#define Wf 128
#define HH 512
#define WH 512
#define C  64
#define NQ (HH*WH)

typedef unsigned long long u64;

// ---- packed f32x2 helpers (sm_100+) ----
__device__ __forceinline__ u64 pk2(float lo, float hi) {
    u64 r; asm("mov.b64 %0, {%1,%2};" : "=l"(r) : "f"(lo), "f"(hi)); return r;
}
__device__ __forceinline__ void fma2(u64 &d, u64 a, u64 b) {
    asm("fma.rn.f32x2 %0, %1, %2, %0;" : "+l"(d) : "l"(a), "l"(b));
}
__device__ __forceinline__ float2 upk2(u64 a) {
    float2 f; asm("mov.b64 {%0,%1}, %2;" : "=f"(f.x), "=f"(f.y) : "l"(a)); return f;
}

// ---- device scratch (static allocation only) ----
// Plane-of-float4 layout: plane i holds channels [4i, 4i+4)
__device__ float4 g_feat[16*Hf*Wf];            //  4 MB
__device__ float4 g_body[(size_t)16*HH*WH];    // 64 MB
__device__ float4 g_pred4[(size_t)HH*WH];      //  4 MB (rgb + pad)
__device__ float  g_Wc[16*8*C];                // [ph][k][c]
__device__ float  g_We[16*8*C];                // [ph][k][c]  (relayout!)
__device__ float  g_off[16*2];                 // [ph][{x,y}]

// ======================================================================
// Kernel 1: encoder conv 3x3, 3->64, pad 1 -> plane layout
// ======================================================================
__global__ __launch_bounds__(256) void enc_kernel(
    const float* __restrict__ inp, const float* __restrict__ ew,
    const float* __restrict__ eb)
{
    __shared__ float sw[64*27];
    __shared__ float sb[64];
    int tid = threadIdx.y*16 + threadIdx.x;
    for (int i = tid; i < 64*27; i += 256) sw[i] = ew[i];
    if (tid < 64) sb[tid] = eb[tid];
    __syncthreads();

    int x = blockIdx.x*16 + threadIdx.x;
    int y = blockIdx.y*16 + threadIdx.y;

    float v[27];
#pragma unroll
    for (int ci = 0; ci < 3; ci++)
#pragma unroll
        for (int ky = 0; ky < 3; ky++)
#pragma unroll
            for (int kx = 0; kx < 3; kx++) {
                int yy = y + ky - 1, xx = x + kx - 1;
                float t = 0.f;
                if ((unsigned)yy < (unsigned)Hf && (unsigned)xx < (unsigned)Wf)
                    t = inp[ci*(Hf*Wf) + yy*Wf + xx];
                v[ci*9 + ky*3 + kx] = t;
            }

    int pix = y*Wf + x;
#pragma unroll
    for (int i = 0; i < 16; i++) {
        float o4[4];
#pragma unroll
        for (int j = 0; j < 4; j++) {
            int o = 4*i + j;
            float acc = sb[o];
            const float* wp = sw + o*27;
#pragma unroll
            for (int t = 0; t < 27; t++) acc += v[t]*wp[t];
            o4[j] = acc;
        }
        g_feat[i*(Hf*Wf) + pix] = make_float4(o4[0], o4[1], o4[2], o4[3]);
    }
}

// ======================================================================
// Kernel 2: 16-phase MLP collapse. g_We now stored [ph][k][c].
// ======================================================================
__global__ void phase_kernel(
    const float* __restrict__ w1, const float* __restrict__ b1,
    const float* __restrict__ w2, const float* __restrict__ b2,
    const float* __restrict__ rw, const float* __restrict__ rb,
    const float* __restrict__ ow, const float* __restrict__ ob,
    const float* __restrict__ wc, const float* __restrict__ we)
{
    __shared__ float semb1[16][64];
    __shared__ float semb2[16][64];
    __shared__ float sr[16][4];

    int c  = threadIdx.x;   // 0..63
    int ph = threadIdx.y;   // 0..15 : ph = (y&3)*4 + (x&3)

    float chh = -0.375f + 0.25f*(float)(ph >> 2);
    float cww = -0.375f + 0.25f*(float)(ph & 3);

    float a = b1[c] + 0.25f*w1[c*4+0] + 0.25f*w1[c*4+1]
            + chh*w1[c*4+2] + cww*w1[c*4+3];
    semb1[ph][c] = fmaxf(a, 0.f);
    __syncthreads();

    float acc = b2[c];
#pragma unroll 8
    for (int j = 0; j < 64; j++) acc += w2[c*64 + j]*semb1[ph][j];
    semb2[ph][c] = fmaxf(acc, 0.f);
    __syncthreads();

    if (c < 4) {
        float s = rb[c];
        for (int j = 0; j < 64; j++) s += rw[c*64 + j]*semb2[ph][j];
        sr[ph][c] = 1.f/(1.f + expf(-s));
    } else if (c < 6) {
        int o = c - 4;
        float s = ob[o];
        for (int j = 0; j < 64; j++) s += ow[o*64 + j]*semb2[ph][j];
        g_off[ph*2 + o] = s;
    }
    __syncthreads();

    float r0 = sr[ph][0], r1 = sr[ph][1], r2 = sr[ph][2], r3 = sr[ph][3];
#pragma unroll
    for (int k = 0; k < 8; k++) {
        // Wc_eff[ph][k][c]
        g_Wc[ph*512 + k*64 + c] =
            r0*wc[0*512 + k*64 + c] + r1*wc[1*512 + k*64 + c] +
            r2*wc[2*512 + k*64 + c] + r3*wc[3*512 + k*64 + c];
        // We_eff[ph][k][c]  (we input layout: [e][c][k])
        g_We[ph*512 + k*64 + c] =
            r0*we[0*512 + c*8 + k] + r1*we[1*512 + c*8 + k] +
            r2*we[2*512 + c*8 + k] + r3*we[3*512 + c*8 + k];
    }
}

// ======================================================================
// Kernel 3: main pixel kernel — packed f32x2 math throughout
// ======================================================================
__global__ __launch_bounds__(256) void main_kernel()
{
    __shared__ __align__(16) float sWc[512];
    __shared__ __align__(16) float sWe[512];
    __shared__ float soff[2];

    int ph  = blockIdx.z;
    int tid = threadIdx.y*16 + threadIdx.x;
    for (int i = tid; i < 512; i += 256) {
        sWc[i] = g_Wc[ph*512 + i];
        sWe[i] = g_We[ph*512 + i];
    }
    if (tid < 2) soff[tid] = g_off[ph*2 + tid];
    __syncthreads();

    int x = blockIdx.x*64 + threadIdx.x*4 + (ph & 3);
    int y = blockIdx.y*64 + threadIdx.y*4 + (ph >> 2);

    float px = ((float)x + 0.5f)*0.25f - 0.5f + soff[0];
    float py = ((float)y + 0.5f)*0.25f - 0.5f + soff[1];

    float x0f = floorf(px), y0f = floorf(py);
    float fx = px - x0f, fy = py - y0f;
    int x0 = (int)x0f, y0 = (int)y0f;
    int x1 = x0 + 1,   y1 = y0 + 1;

    float w00 = (1.f-fy)*(1.f-fx), w01 = (1.f-fy)*fx;
    float w10 = fy*(1.f-fx),       w11 = fy*fx;

    bool vx0 = (unsigned)x0 < 128u, vx1 = (unsigned)x1 < 128u;
    bool vy0 = (unsigned)y0 < 128u, vy1 = (unsigned)y1 < 128u;
    if (!(vy0 && vx0)) w00 = 0.f;
    if (!(vy0 && vx1)) w01 = 0.f;
    if (!(vy1 && vx0)) w10 = 0.f;
    if (!(vy1 && vx1)) w11 = 0.f;

    int x0c = min(max(x0,0),127), x1c = min(max(x1,0),127);
    int y0c = min(max(y0,0),127), y1c = min(max(y1,0),127);

    int i00 = y0c*Wf + x0c, i01 = y0c*Wf + x1c;
    int i10 = y1c*Wf + x0c, i11 = y1c*Wf + x1c;

    u64 W00 = pk2(w00,w00), W01 = pk2(w01,w01);
    u64 W10 = pk2(w10,w10), W11 = pk2(w11,w11);

    // bilinear gather -> packed fea pairs (fea2[2i] = ch {4i,4i+1})
    u64 fea2[32];
#pragma unroll
    for (int i = 0; i < 16; i++) {
        const ulonglong2* pl = (const ulonglong2*)(g_feat + i*(Hf*Wf));
        ulonglong2 a = pl[i00], b = pl[i01], cc = pl[i10], d = pl[i11];
        u64 e0 = 0, e1 = 0;
        fma2(e0, a.x, W00); fma2(e0, b.x, W01); fma2(e0, cc.x, W10); fma2(e0, d.x, W11);
        fma2(e1, a.y, W00); fma2(e1, b.y, W01); fma2(e1, cc.y, W10); fma2(e1, d.y, W11);
        fea2[2*i] = e0; fea2[2*i+1] = e1;
    }

    // mid = Wc_eff @ fea  (8x64), packed + horizontal reduce
    const ulonglong2* wc2 = (const ulonglong2*)sWc;
    u64 mid2[8];
#pragma unroll
    for (int k = 0; k < 8; k++) {
        u64 acc = 0;
#pragma unroll
        for (int i = 0; i < 16; i++) {
            ulonglong2 w = wc2[k*16 + i];
            fma2(acc, fea2[2*i],   w.x);
            fma2(acc, fea2[2*i+1], w.y);
        }
        float2 f = upk2(acc);
        float m = f.x + f.y;
        mid2[k] = pk2(m, m);
    }

    // body = We_eff^T @ mid + fea  -> plane layout
    const u64* we2 = (const u64*)sWe;   // [k][32 c-pairs]
    size_t pix = (size_t)y*WH + x;
#pragma unroll
    for (int i = 0; i < 16; i++) {
        u64 o0 = fea2[2*i], o1 = fea2[2*i+1];
#pragma unroll
        for (int k = 0; k < 8; k++) {
            fma2(o0, mid2[k], we2[k*32 + 2*i]);
            fma2(o1, mid2[k], we2[k*32 + 2*i+1]);
        }
        ulonglong2 o; o.x = o0; o.y = o1;
        *((ulonglong2*)(g_body + (size_t)i*(HH*WH) + pix)) = o;
    }
}

// ======================================================================
// Kernel 4: tail conv 3x3, 64->3, pad 1. smem-tiled body + packed FMA.
// Block 32x8 outputs; tile (34 x 10) x 16 planes in dynamic smem (87KB).
// ======================================================================
#define TILE_ELEMS (16*10*34)
__global__ __launch_bounds__(256) void tail_kernel(
    const float* __restrict__ tw, const float* __restrict__ tb)
{
    extern __shared__ __align__(16) char smem_dyn[];
    float4* tile = (float4*)smem_dyn;                    // [pl][ry][rx] 34-wide
    float*  sw   = (float*)(smem_dyn + TILE_ELEMS*16);   // [o][p][c] 1728 floats

    int tid = threadIdx.y*32 + threadIdx.x;
    for (int idx = tid; idx < 1728; idx += 256) {
        int o = idx/576, rem = idx%576, p = rem/64, c = rem%64;
        sw[idx] = tw[o*576 + c*9 + p];
    }

    int bx = blockIdx.x*32, by = blockIdx.y*8;
    for (int idx = tid; idx < TILE_ELEMS; idx += 256) {
        int pl = idx / 340, rem = idx % 340;
        int ry = rem / 34,  rx = rem % 34;
        int gy = by + ry - 1, gx = bx + rx - 1;
        float4 v = make_float4(0.f, 0.f, 0.f, 0.f);
        if ((unsigned)gy < (unsigned)HH && (unsigned)gx < (unsigned)WH)
            v = g_body[(size_t)pl*(HH*WH) + (size_t)gy*WH + gx];
        tile[idx] = v;
    }
    __syncthreads();

    int tx = threadIdx.x, ty = threadIdx.y;
    u64 acc0 = 0, acc1 = 0, acc2 = 0;

    for (int pl = 0; pl < 16; pl++) {
#pragma unroll
        for (int dy = 0; dy < 3; dy++) {
#pragma unroll
            for (int dx = 0; dx < 3; dx++) {
                int p = dy*3 + dx;
                ulonglong2 v = *(const ulonglong2*)&tile[(pl*10 + ty+dy)*34 + tx+dx];
                ulonglong2 u0 = *(const ulonglong2*)(sw +          p*64 + 4*pl);
                ulonglong2 u1 = *(const ulonglong2*)(sw +  576 +   p*64 + 4*pl);
                ulonglong2 u2 = *(const ulonglong2*)(sw + 1152 +   p*64 + 4*pl);
                fma2(acc0, v.x, u0.x); fma2(acc0, v.y, u0.y);
                fma2(acc1, v.x, u1.x); fma2(acc1, v.y, u1.y);
                fma2(acc2, v.x, u2.x); fma2(acc2, v.y, u2.y);
            }
        }
    }

    float2 f0 = upk2(acc0), f1 = upk2(acc1), f2 = upk2(acc2);
    float4 o;
    o.x = tb[0] + f0.x + f0.y;
    o.y = tb[1] + f1.x + f1.y;
    o.z = tb[2] + f2.x + f2.y;
    o.w = 0.f;
    g_pred4[(size_t)(by+ty)*WH + (bx+tx)] = o;
}

// ======================================================================
// Kernel 5: nearest-neighbor query gather (single float4 load)
// ======================================================================
__global__ void query_kernel(const float* __restrict__ coord,
                             const float* __restrict__ cell,
                             float* __restrict__ out)
{
    int q = blockIdx.x*256 + threadIdx.x;
    if (q >= NQ) return;
    float gy = coord[2*q+0] - cell[2*q+0]*0.5f + 1e-6f;
    float gx = coord[2*q+1] - cell[2*q+1]*0.5f + 1e-6f;
    gy = fminf(fmaxf(gy, -1.f + 1e-6f), 1.f - 1e-6f);
    gx = fminf(fmaxf(gx, -1.f + 1e-6f), 1.f - 1e-6f);
    int xi = (int)rintf((gx + 1.f)*0.5f*511.f);
    int yi = (int)rintf((gy + 1.f)*0.5f*511.f);
    xi = min(max(xi, 0), 511);
    yi = min(max(yi, 0), 511);
    float4 v = g_pred4[(size_t)yi*WH + xi];
    out[3*q+0] = v.x;
    out[3*q+1] = v.y;
    out[3*q+2] = v.z;
}

// ======================================================================
extern "C" void kernel_launch(void* const* d_in, const int* in_sizes, int n_in,
                              void* d_out, int out_size)
{
    const float* inp   = (const float*)d_in[0];
    const float* coord = (const float*)d_in[1];
    const float* cell  = (const float*)d_in[2];
    const float* enc_w = (const float*)d_in[3];
    const float* enc_b = (const float*)d_in[4];
    const float* w1    = (const float*)d_in[5];
    const float* b1    = (const float*)d_in[6];
    const float* w2    = (const float*)d_in[7];
    const float* b2    = (const float*)d_in[8];
    const float* rw    = (const float*)d_in[9];
    const float* rb    = (const float*)d_in[10];
    const float* ow    = (const float*)d_in[11];
    const float* ob    = (const float*)d_in[12];
    const float* tw    = (const float*)d_in[13];
    const float* tb    = (const float*)d_in[14];
    const float* wc    = (const float*)d_in[15];
    const float* we    = (const float*)d_in[16];
    float* out = (float*)d_out;

    const int tail_smem = TILE_ELEMS*16 + 1728*4;   // 87040 + 6912 = 93952 B
    cudaFuncSetAttribute(tail_kernel,
                         cudaFuncAttributeMaxDynamicSharedMemorySize, tail_smem);

    enc_kernel<<<dim3(8,8), dim3(16,16)>>>(inp, enc_w, enc_b);
    phase_kernel<<<1, dim3(64,16)>>>(w1,b1,w2,b2,rw,rb,ow,ob,wc,we);
    main_kernel<<<dim3(8,8,16), dim3(16,16)>>>();
    tail_kernel<<<dim3(16,64), dim3(32,8), tail_smem>>>(tw, tb);
    query_kernel<<<NQ/256, 256>>>(coord, cell, out);
}

// round 17
// speedup vs baseline: 1.1558x; 1.1558x over previous
#include <cuda_runtime.h>
#include <math.h>

#define Hf 128
#define Wf 128
#define HH 512
#define WH 512
#define C  64
#define NQ (HH*WH)

typedef unsigned long long u64;

// ---- packed f32x2 helpers (sm_100+) ----
__device__ __forceinline__ u64 pk2(float lo, float hi) {
    u64 r; asm("mov.b64 %0, {%1,%2};" : "=l"(r) : "f"(lo), "f"(hi)); return r;
}
__device__ __forceinline__ void fma2(u64 &d, u64 a, u64 b) {
    asm("fma.rn.f32x2 %0, %1, %2, %0;" : "+l"(d) : "l"(a), "l"(b));
}
__device__ __forceinline__ float2 upk2(u64 a) {
    float2 f; asm("mov.b64 {%0,%1}, %2;" : "=f"(f.x), "=f"(f.y) : "l"(a)); return f;
}

// ---- device scratch (static allocation only) ----
// Plane-of-float4 layout: plane i holds channels [4i, 4i+4)
__device__ float4 g_feat[16*Hf*Wf];            //  4 MB
__device__ float4 g_body[(size_t)16*HH*WH];    // 64 MB
__device__ float4 g_pred4[(size_t)HH*WH];      //  4 MB (rgb + pad)
__device__ float  g_Wc[16*8*C];                // [ph][k][c]
__device__ float  g_We[16*8*C];                // [ph][k][c]
__device__ float  g_off[16*2];                 // [ph][{x,y}]

// ======================================================================
// Kernel 1: encoder conv 3x3, 3->64, pad 1 -> plane layout
// ======================================================================
__global__ __launch_bounds__(256) void enc_kernel(
    const float* __restrict__ inp, const float* __restrict__ ew,
    const float* __restrict__ eb)
{
    __shared__ float sw[64*27];
    __shared__ float sb[64];
    int tid = threadIdx.y*16 + threadIdx.x;
    for (int i = tid; i < 64*27; i += 256) sw[i] = ew[i];
    if (tid < 64) sb[tid] = eb[tid];
    __syncthreads();

    int x = blockIdx.x*16 + threadIdx.x;
    int y = blockIdx.y*16 + threadIdx.y;

    float v[27];
#pragma unroll
    for (int ci = 0; ci < 3; ci++)
#pragma unroll
        for (int ky = 0; ky < 3; ky++)
#pragma unroll
            for (int kx = 0; kx < 3; kx++) {
                int yy = y + ky - 1, xx = x + kx - 1;
                float t = 0.f;
                if ((unsigned)yy < (unsigned)Hf && (unsigned)xx < (unsigned)Wf)
                    t = inp[ci*(Hf*Wf) + yy*Wf + xx];
                v[ci*9 + ky*3 + kx] = t;
            }

    int pix = y*Wf + x;
#pragma unroll
    for (int i = 0; i < 16; i++) {
        float o4[4];
#pragma unroll
        for (int j = 0; j < 4; j++) {
            int o = 4*i + j;
            float acc = sb[o];
            const float* wp = sw + o*27;
#pragma unroll
            for (int t = 0; t < 27; t++) acc += v[t]*wp[t];
            o4[j] = acc;
        }
        g_feat[i*(Hf*Wf) + pix] = make_float4(o4[0], o4[1], o4[2], o4[3]);
    }
}

// ======================================================================
// Kernel 2: 16-phase MLP collapse. g_We stored [ph][k][c].
// ======================================================================
__global__ void phase_kernel(
    const float* __restrict__ w1, const float* __restrict__ b1,
    const float* __restrict__ w2, const float* __restrict__ b2,
    const float* __restrict__ rw, const float* __restrict__ rb,
    const float* __restrict__ ow, const float* __restrict__ ob,
    const float* __restrict__ wc, const float* __restrict__ we)
{
    __shared__ float semb1[16][64];
    __shared__ float semb2[16][64];
    __shared__ float sr[16][4];

    int c  = threadIdx.x;   // 0..63
    int ph = threadIdx.y;   // 0..15 : ph = (y&3)*4 + (x&3)

    float chh = -0.375f + 0.25f*(float)(ph >> 2);
    float cww = -0.375f + 0.25f*(float)(ph & 3);

    float a = b1[c] + 0.25f*w1[c*4+0] + 0.25f*w1[c*4+1]
            + chh*w1[c*4+2] + cww*w1[c*4+3];
    semb1[ph][c] = fmaxf(a, 0.f);
    __syncthreads();

    float acc = b2[c];
#pragma unroll 8
    for (int j = 0; j < 64; j++) acc += w2[c*64 + j]*semb1[ph][j];
    semb2[ph][c] = fmaxf(acc, 0.f);
    __syncthreads();

    if (c < 4) {
        float s = rb[c];
        for (int j = 0; j < 64; j++) s += rw[c*64 + j]*semb2[ph][j];
        sr[ph][c] = 1.f/(1.f + expf(-s));
    } else if (c < 6) {
        int o = c - 4;
        float s = ob[o];
        for (int j = 0; j < 64; j++) s += ow[o*64 + j]*semb2[ph][j];
        g_off[ph*2 + o] = s;
    }
    __syncthreads();

    float r0 = sr[ph][0], r1 = sr[ph][1], r2 = sr[ph][2], r3 = sr[ph][3];
#pragma unroll
    for (int k = 0; k < 8; k++) {
        g_Wc[ph*512 + k*64 + c] =
            r0*wc[0*512 + k*64 + c] + r1*wc[1*512 + k*64 + c] +
            r2*wc[2*512 + k*64 + c] + r3*wc[3*512 + k*64 + c];
        g_We[ph*512 + k*64 + c] =
            r0*we[0*512 + c*8 + k] + r1*we[1*512 + c*8 + k] +
            r2*we[2*512 + c*8 + k] + r3*we[3*512 + c*8 + k];
    }
}

// ======================================================================
// Kernel 3: main pixel kernel — packed f32x2 math (round-16 version)
// ======================================================================
__global__ __launch_bounds__(256) void main_kernel()
{
    __shared__ __align__(16) float sWc[512];
    __shared__ __align__(16) float sWe[512];
    __shared__ float soff[2];

    int ph  = blockIdx.z;
    int tid = threadIdx.y*16 + threadIdx.x;
    for (int i = tid; i < 512; i += 256) {
        sWc[i] = g_Wc[ph*512 + i];
        sWe[i] = g_We[ph*512 + i];
    }
    if (tid < 2) soff[tid] = g_off[ph*2 + tid];
    __syncthreads();

    int x = blockIdx.x*64 + threadIdx.x*4 + (ph & 3);
    int y = blockIdx.y*64 + threadIdx.y*4 + (ph >> 2);

    float px = ((float)x + 0.5f)*0.25f - 0.5f + soff[0];
    float py = ((float)y + 0.5f)*0.25f - 0.5f + soff[1];

    float x0f = floorf(px), y0f = floorf(py);
    float fx = px - x0f, fy = py - y0f;
    int x0 = (int)x0f, y0 = (int)y0f;
    int x1 = x0 + 1,   y1 = y0 + 1;

    float w00 = (1.f-fy)*(1.f-fx), w01 = (1.f-fy)*fx;
    float w10 = fy*(1.f-fx),       w11 = fy*fx;

    bool vx0 = (unsigned)x0 < 128u, vx1 = (unsigned)x1 < 128u;
    bool vy0 = (unsigned)y0 < 128u, vy1 = (unsigned)y1 < 128u;
    if (!(vy0 && vx0)) w00 = 0.f;
    if (!(vy0 && vx1)) w01 = 0.f;
    if (!(vy1 && vx0)) w10 = 0.f;
    if (!(vy1 && vx1)) w11 = 0.f;

    int x0c = min(max(x0,0),127), x1c = min(max(x1,0),127);
    int y0c = min(max(y0,0),127), y1c = min(max(y1,0),127);

    int i00 = y0c*Wf + x0c, i01 = y0c*Wf + x1c;
    int i10 = y1c*Wf + x0c, i11 = y1c*Wf + x1c;

    u64 W00 = pk2(w00,w00), W01 = pk2(w01,w01);
    u64 W10 = pk2(w10,w10), W11 = pk2(w11,w11);

    u64 fea2[32];
#pragma unroll
    for (int i = 0; i < 16; i++) {
        const ulonglong2* pl = (const ulonglong2*)(g_feat + i*(Hf*Wf));
        ulonglong2 a = pl[i00], b = pl[i01], cc = pl[i10], d = pl[i11];
        u64 e0 = 0, e1 = 0;
        fma2(e0, a.x, W00); fma2(e0, b.x, W01); fma2(e0, cc.x, W10); fma2(e0, d.x, W11);
        fma2(e1, a.y, W00); fma2(e1, b.y, W01); fma2(e1, cc.y, W10); fma2(e1, d.y, W11);
        fea2[2*i] = e0; fea2[2*i+1] = e1;
    }

    const ulonglong2* wc2 = (const ulonglong2*)sWc;
    u64 mid2[8];
#pragma unroll
    for (int k = 0; k < 8; k++) {
        u64 acc = 0;
#pragma unroll
        for (int i = 0; i < 16; i++) {
            ulonglong2 w = wc2[k*16 + i];
            fma2(acc, fea2[2*i],   w.x);
            fma2(acc, fea2[2*i+1], w.y);
        }
        float2 f = upk2(acc);
        float m = f.x + f.y;
        mid2[k] = pk2(m, m);
    }

    const u64* we2 = (const u64*)sWe;   // [k][32 c-pairs]
    size_t pix = (size_t)y*WH + x;
#pragma unroll
    for (int i = 0; i < 16; i++) {
        u64 o0 = fea2[2*i], o1 = fea2[2*i+1];
#pragma unroll
        for (int k = 0; k < 8; k++) {
            fma2(o0, mid2[k], we2[k*32 + 2*i]);
            fma2(o1, mid2[k], we2[k*32 + 2*i+1]);
        }
        ulonglong2 o; o.x = o0; o.y = o1;
        *((ulonglong2*)(g_body + (size_t)i*(HH*WH) + pix)) = o;
    }
}

// ======================================================================
// Kernel 4: tail conv 3x3, 64->3, pad 1.
// Direct LDG (L2-cached body), 4-pixel y-strip per thread for row reuse,
// per-plane weights hoisted into registers, packed f32x2 FMA.
// Block 32x8 threads -> 32x32 output tile. Grid (16,16).
// ======================================================================
__global__ __launch_bounds__(256) void tail_kernel(
    const float* __restrict__ tw, const float* __restrict__ tb)
{
    __shared__ __align__(16) float sw[3*576];   // [o][p][c]
    int tid = threadIdx.y*32 + threadIdx.x;
    for (int idx = tid; idx < 1728; idx += 256) {
        int o = idx/576, rem = idx%576, p = rem/64, c = rem%64;
        sw[idx] = tw[o*576 + c*9 + p];
    }
    __syncthreads();

    int x  = blockIdx.x*32 + threadIdx.x;
    int y0 = (blockIdx.y*8 + threadIdx.y)*4;

    u64 acc[3][4];
#pragma unroll
    for (int o = 0; o < 3; o++)
#pragma unroll
        for (int i = 0; i < 4; i++) acc[o][i] = 0;

    for (int pl = 0; pl < 16; pl++) {
        // hoist this plane's 27 weight-vector pairs into registers
        ulonglong2 w[3][9];
#pragma unroll
        for (int o = 0; o < 3; o++)
#pragma unroll
            for (int p = 0; p < 9; p++)
                w[o][p] = *(const ulonglong2*)(sw + o*576 + p*64 + 4*pl);

        const float4* plane = g_body + (size_t)pl*(HH*WH);
#pragma unroll
        for (int r = 0; r < 6; r++) {
            int gy = y0 - 1 + r;
            ulonglong2 vL, vC, vR;
            vL.x = vL.y = vC.x = vC.y = vR.x = vR.y = 0ull;
            if ((unsigned)gy < (unsigned)HH) {
                const ulonglong2* row = (const ulonglong2*)(plane + (size_t)gy*WH);
                vC = row[x];
                if (x > 0)      vL = row[x-1];
                if (x < WH-1)   vR = row[x+1];
            }
#pragma unroll
            for (int i = 0; i < 4; i++) {
                int dy = r - i;
                if (dy < 0 || dy > 2) continue;   // compile-time pruned
#pragma unroll
                for (int dx = 0; dx < 3; dx++) {
                    int p = dy*3 + dx;
                    ulonglong2 v = (dx == 0) ? vL : ((dx == 1) ? vC : vR);
#pragma unroll
                    for (int o = 0; o < 3; o++) {
                        fma2(acc[o][i], v.x, w[o][p].x);
                        fma2(acc[o][i], v.y, w[o][p].y);
                    }
                }
            }
        }
    }

    float b0 = tb[0], b1 = tb[1], b2 = tb[2];
#pragma unroll
    for (int i = 0; i < 4; i++) {
        float2 f0 = upk2(acc[0][i]), f1 = upk2(acc[1][i]), f2 = upk2(acc[2][i]);
        float4 o;
        o.x = b0 + f0.x + f0.y;
        o.y = b1 + f1.x + f1.y;
        o.z = b2 + f2.x + f2.y;
        o.w = 0.f;
        g_pred4[(size_t)(y0+i)*WH + x] = o;
    }
}

// ======================================================================
// Kernel 5: nearest-neighbor query gather (single float4 load)
// ======================================================================
__global__ void query_kernel(const float* __restrict__ coord,
                             const float* __restrict__ cell,
                             float* __restrict__ out)
{
    int q = blockIdx.x*256 + threadIdx.x;
    if (q >= NQ) return;
    float gy = coord[2*q+0] - cell[2*q+0]*0.5f + 1e-6f;
    float gx = coord[2*q+1] - cell[2*q+1]*0.5f + 1e-6f;
    gy = fminf(fmaxf(gy, -1.f + 1e-6f), 1.f - 1e-6f);
    gx = fminf(fmaxf(gx, -1.f + 1e-6f), 1.f - 1e-6f);
    int xi = (int)rintf((gx + 1.f)*0.5f*511.f);
    int yi = (int)rintf((gy + 1.f)*0.5f*511.f);
    xi = min(max(xi, 0), 511);
    yi = min(max(yi, 0), 511);
    float4 v = g_pred4[(size_t)yi*WH + xi];
    out[3*q+0] = v.x;
    out[3*q+1] = v.y;
    out[3*q+2] = v.z;
}

// ======================================================================
extern "C" void kernel_launch(void* const* d_in, const int* in_sizes, int n_in,
                              void* d_out, int out_size)
{
    const float* inp   = (const float*)d_in[0];
    const float* coord = (const float*)d_in[1];
    const float* cell  = (const float*)d_in[2];
    const float* enc_w = (const float*)d_in[3];
    const float* enc_b = (const float*)d_in[4];
    const float* w1    = (const float*)d_in[5];
    const float* b1    = (const float*)d_in[6];
    const float* w2    = (const float*)d_in[7];
    const float* b2    = (const float*)d_in[8];
    const float* rw    = (const float*)d_in[9];
    const float* rb    = (const float*)d_in[10];
    const float* ow    = (const float*)d_in[11];
    const float* ob    = (const float*)d_in[12];
    const float* tw    = (const float*)d_in[13];
    const float* tb    = (const float*)d_in[14];
    const float* wc    = (const float*)d_in[15];
    const float* we    = (const float*)d_in[16];
    float* out = (float*)d_out;

    enc_kernel<<<dim3(8,8), dim3(16,16)>>>(inp, enc_w, enc_b);
    phase_kernel<<<1, dim3(64,16)>>>(w1,b1,w2,b2,rw,rb,ow,ob,wc,we);
    main_kernel<<<dim3(8,8,16), dim3(16,16)>>>();
    tail_kernel<<<dim3(16,16), dim3(32,8)>>>(tw, tb);
    query_kernel<<<NQ/256, 256>>>(coord, cell, out);
}